// round 10
// baseline (speedup 1.0000x reference)
#include <cuda_runtime.h>
#include <cuda_bf16.h>
#include <cstddef>
#include <cstdint>

#define D 128
#define MAXG 100000

// scratch (device globals — no allocation allowed)
__device__ int   g_last[MAXG];
__device__ float g_A[D * D];
__device__ float g_bp[D];
__device__ float g_p[(size_t)MAXG * D];
__device__ float g_s[(size_t)MAXG * D];
// bf16 hi/lo splits of the two B matrices, stored as b_eff[n][k]
__device__ __nv_bfloat16 g_B1h[D * D], g_B1l[D * D];
__device__ __nv_bfloat16 g_B2h[D * D], g_B2l[D * D];

// ---------------------------------------------------------------- helpers
__device__ __forceinline__ float lo_of(float v) {
    return v - __bfloat162float(__float2bfloat16(v));
}
__device__ __forceinline__ uint32_t pack2(float a, float b) {
    __nv_bfloat162 h;
    h.x = __float2bfloat16(a);
    h.y = __float2bfloat16(b);
    return *(uint32_t*)&h;
}
__device__ __forceinline__ uint32_t smem_u32(const void* p) {
    uint32_t a;
    asm("{ .reg .u64 t; cvta.to.shared.u64 t, %1; cvt.u32.u64 %0, t; }"
        : "=r"(a) : "l"(p));
    return a;
}

#define MMA_BF16(cc, a0, a1, a2, a3, b0, b1)                                  \
    asm volatile(                                                             \
        "mma.sync.aligned.m16n8k16.row.col.f32.bf16.bf16.f32 "                \
        "{%0,%1,%2,%3}, {%4,%5,%6,%7}, {%8,%9}, {%0,%1,%2,%3};"               \
        : "+f"(cc[0]), "+f"(cc[1]), "+f"(cc[2]), "+f"(cc[3])                  \
        : "r"(a0), "r"(a1), "r"(a2), "r"(a3), "r"(b0), "r"(b1))

#define LDSM_X4(r, addr)                                                      \
    asm volatile("ldmatrix.sync.aligned.m8n8.x4.shared.b16 {%0,%1,%2,%3}, [%4];" \
                 : "=r"(r[0]), "=r"(r[1]), "=r"(r[2]), "=r"(r[3])             \
                 : "r"(addr))

// -------------------------------------------------------------------------
// 1) segment boundaries
// -------------------------------------------------------------------------
__global__ void bounds_kernel(const int* __restrict__ seg, int N) {
    int i = blockIdx.x * blockDim.x + threadIdx.x;
    if (i < N) {
        int sid = seg[i];
        if (i == N - 1 || seg[i + 1] != sid) g_last[sid] = i;
    }
}

// -------------------------------------------------------------------------
// 2) A = Wq^T @ Wk, b' = bq @ Wk
// -------------------------------------------------------------------------
__global__ void prep_kernel(const float* __restrict__ Wq, const float* __restrict__ bq,
                            const float* __restrict__ Wk) {
    int t = threadIdx.x;
    if (blockIdx.x < 64) {
        int idx = blockIdx.x * 256 + t;
        int i = idx >> 7, j = idx & 127;
        float sum = 0.f;
#pragma unroll 8
        for (int d = 0; d < D; d++) sum += Wq[d * D + i] * Wk[d * D + j];
        g_A[idx] = sum;
    } else if (t < D) {
        float sum = 0.f;
#pragma unroll 8
        for (int d = 0; d < D; d++) sum += bq[d] * Wk[d * D + t];
        g_bp[t] = sum;
    }
}

// -------------------------------------------------------------------------
// 2b) bf16 hi/lo split of both B matrices (b_eff[n][k] layout)
// -------------------------------------------------------------------------
__global__ void split_kernel(const float* __restrict__ Wk) {
    int idx = blockIdx.x * 256 + threadIdx.x;
    int n = idx >> 7, k = idx & 127;
    float v1 = g_A[k * D + n];
    g_B1h[idx] = __float2bfloat16(v1);
    g_B1l[idx] = __float2bfloat16(lo_of(v1));
    float v2 = Wk[idx];
    g_B2h[idx] = __float2bfloat16(v2);
    g_B2l[idx] = __float2bfloat16(lo_of(v2));
}

// -------------------------------------------------------------------------
// Tensor-core GEMM via mma.sync + ldmatrix, pipelined:
//   C[M,128] = rows(Amat) @ b_eff^T + bias
//   3-term bf16 split (hi*hi + lo*hi + hi*lo), fp32 accumulate.
//   B (hi/lo, full K) staged ONCE; A double-buffered in KC=32 chunks with
//   register prefetch. CTA tile 128x128, 256 thr, warp tile 32x64.
// -------------------------------------------------------------------------
#define KC     32
#define BSROW  272                    // B row stride bytes (256 + 16)
#define ASROW  80                     // A row stride bytes (64 + 16)
#define OFF_BH 0
#define OFF_BL (128 * BSROW)          // 34816
#define OFF_A  (2 * 128 * BSROW)      // 69632
#define ABUF   (2 * 128 * ASROW)      // 20480 per buffer (AH+AL)
#define AHALF  (128 * ASROW)          // 10240
#define SMEM_TOT (OFF_A + 2 * ABUF)   // 110592 B -> 2 CTAs/SM

__global__ void __launch_bounds__(256)
mma_gemm_kernel(const float* __restrict__ Amat,
                const __nv_bfloat16* __restrict__ Bh,
                const __nv_bfloat16* __restrict__ Bl,
                const float* __restrict__ bias,
                const int* __restrict__ ridx,
                float* __restrict__ C, int M) {
    extern __shared__ char smem[];
    uint32_t sb = smem_u32(smem);
    int t = threadIdx.x, lane = t & 31, w = t >> 5;
    int mBase = blockIdx.x * 128;

    // staging mapping: 2 threads per row
    int row = t >> 1;
    int half = t & 1;

    // ---- stage B (full K), one time ----
    {
        const uint4* bhp = (const uint4*)(Bh + row * D + half * 64);
        const uint4* blp = (const uint4*)(Bl + row * D + half * 64);
        uint4* dh = (uint4*)(smem + OFF_BH + row * BSROW + half * 128);
        uint4* dl = (uint4*)(smem + OFF_BL + row * BSROW + half * 128);
#pragma unroll
        for (int j = 0; j < 8; j++) {
            dh[j] = bhp[j];
            dl[j] = blp[j];
        }
    }

    // A source pointer (16 k-elements per thread per chunk)
    int m = mBase + row;
    if (m >= M) m = M - 1;
    int ar = ridx ? ridx[m] : m;
    const float* ap = Amat + (size_t)ar * D + half * 16;
    char* sAh_base = smem + OFF_A + row * ASROW + half * 32;

    // ---- stage A chunk 0 ----
    {
        float4 p0 = *(const float4*)(ap + 0);
        float4 p1 = *(const float4*)(ap + 4);
        float4 p2 = *(const float4*)(ap + 8);
        float4 p3 = *(const float4*)(ap + 12);
        uint4 h0 = {pack2(p0.x, p0.y), pack2(p0.z, p0.w), pack2(p1.x, p1.y), pack2(p1.z, p1.w)};
        uint4 h1 = {pack2(p2.x, p2.y), pack2(p2.z, p2.w), pack2(p3.x, p3.y), pack2(p3.z, p3.w)};
        uint4 l0 = {pack2(lo_of(p0.x), lo_of(p0.y)), pack2(lo_of(p0.z), lo_of(p0.w)),
                    pack2(lo_of(p1.x), lo_of(p1.y)), pack2(lo_of(p1.z), lo_of(p1.w))};
        uint4 l1 = {pack2(lo_of(p2.x), lo_of(p2.y)), pack2(lo_of(p2.z), lo_of(p2.w)),
                    pack2(lo_of(p3.x), lo_of(p3.y)), pack2(lo_of(p3.z), lo_of(p3.w))};
        *(uint4*)(sAh_base) = h0;
        *(uint4*)(sAh_base + 16) = h1;
        *(uint4*)(sAh_base + AHALF) = l0;
        *(uint4*)(sAh_base + AHALF + 16) = l1;
    }
    __syncthreads();

    // compute mapping: warp (w&3) -> m rows [32), (w>>2) -> n cols [64)
    int warpM = (w & 3) * 32;
    int warpN = (w >> 2) * 64;
    int ldRow = ((lane >> 3) & 1) * 8 + (lane & 7);
    int ldK16 = (lane >> 4) * 16;
    uint32_t aOff = (uint32_t)((warpM + ldRow) * ASROW + ldK16);
    uint32_t bOff = (uint32_t)((warpN + ldRow) * BSROW + ldK16);

    float acc[2][8][4];
#pragma unroll
    for (int mb = 0; mb < 2; mb++)
#pragma unroll
        for (int nb = 0; nb < 8; nb++)
#pragma unroll
            for (int i = 0; i < 4; i++) acc[mb][nb][i] = 0.f;

#pragma unroll
    for (int kc = 0; kc < 4; kc++) {
        // prefetch next A chunk (global -> regs), overlapped with compute
        float4 p0, p1, p2, p3;
        if (kc < 3) {
            const float* a = ap + (kc + 1) * KC;
            p0 = *(const float4*)(a + 0);
            p1 = *(const float4*)(a + 4);
            p2 = *(const float4*)(a + 8);
            p3 = *(const float4*)(a + 12);
        }

        uint32_t abase = sb + OFF_A + (kc & 1) * ABUF;
        // ---- compute this chunk: 2 k-steps ----
#pragma unroll
        for (int ks = 0; ks < 2; ks++) {
            uint32_t kA = ks * 32;                     // bytes within chunk
            uint32_t kB = (kc * 2 + ks) * 32;          // bytes within full K
            uint32_t ah[2][4], al[2][4];
#pragma unroll
            for (int mb = 0; mb < 2; mb++) {
                uint32_t base = aOff + mb * (16 * ASROW) + kA;
                LDSM_X4(ah[mb], abase + base);
                LDSM_X4(al[mb], abase + AHALF + base);
            }
#pragma unroll
            for (int nb2 = 0; nb2 < 4; nb2++) {
                uint32_t base = bOff + nb2 * (16 * BSROW) + kB;
                uint32_t bh[4], bl[4];
                LDSM_X4(bh, sb + OFF_BH + base);
                LDSM_X4(bl, sb + OFF_BL + base);
#pragma unroll
                for (int mb = 0; mb < 2; mb++) {
                    MMA_BF16(acc[mb][nb2 * 2],     ah[mb][0], ah[mb][1], ah[mb][2], ah[mb][3], bh[0], bh[2]);
                    MMA_BF16(acc[mb][nb2 * 2],     al[mb][0], al[mb][1], al[mb][2], al[mb][3], bh[0], bh[2]);
                    MMA_BF16(acc[mb][nb2 * 2],     ah[mb][0], ah[mb][1], ah[mb][2], ah[mb][3], bl[0], bl[2]);
                    MMA_BF16(acc[mb][nb2 * 2 + 1], ah[mb][0], ah[mb][1], ah[mb][2], ah[mb][3], bh[1], bh[3]);
                    MMA_BF16(acc[mb][nb2 * 2 + 1], al[mb][0], al[mb][1], al[mb][2], al[mb][3], bh[1], bh[3]);
                    MMA_BF16(acc[mb][nb2 * 2 + 1], ah[mb][0], ah[mb][1], ah[mb][2], ah[mb][3], bl[1], bl[3]);
                }
            }
        }

        if (kc < 3) {
            // convert + store prefetched chunk into the other buffer
            char* dst = (char*)smem + OFF_A + ((kc + 1) & 1) * ABUF +
                        row * ASROW + half * 32;
            uint4 h0 = {pack2(p0.x, p0.y), pack2(p0.z, p0.w), pack2(p1.x, p1.y), pack2(p1.z, p1.w)};
            uint4 h1 = {pack2(p2.x, p2.y), pack2(p2.z, p2.w), pack2(p3.x, p3.y), pack2(p3.z, p3.w)};
            uint4 l0 = {pack2(lo_of(p0.x), lo_of(p0.y)), pack2(lo_of(p0.z), lo_of(p0.w)),
                        pack2(lo_of(p1.x), lo_of(p1.y)), pack2(lo_of(p1.z), lo_of(p1.w))};
            uint4 l1 = {pack2(lo_of(p2.x), lo_of(p2.y)), pack2(lo_of(p2.z), lo_of(p2.w)),
                        pack2(lo_of(p3.x), lo_of(p3.y)), pack2(lo_of(p3.z), lo_of(p3.w))};
            *(uint4*)(dst) = h0;
            *(uint4*)(dst + 16) = h1;
            *(uint4*)(dst + AHALF) = l0;
            *(uint4*)(dst + AHALF + 16) = l1;
            __syncthreads();
        }
    }

    // ---- epilogue ----
    int g = lane >> 2, p = lane & 3;
#pragma unroll
    for (int mb = 0; mb < 2; mb++) {
        int r0 = mBase + warpM + mb * 16 + g;
        int r1 = r0 + 8;
#pragma unroll
        for (int nb = 0; nb < 8; nb++) {
            int col = warpN + nb * 8 + p * 2;
            float2 bv = *(const float2*)(bias + col);
            if (r0 < M) {
                float2 o = {acc[mb][nb][0] + bv.x, acc[mb][nb][1] + bv.y};
                *(float2*)(C + (size_t)r0 * D + col) = o;
            }
            if (r1 < M) {
                float2 o = {acc[mb][nb][2] + bv.x, acc[mb][nb][3] + bv.y};
                *(float2*)(C + (size_t)r1 * D + col) = o;
            }
        }
    }
}

// -------------------------------------------------------------------------
// 4) fused per-segment online softmax + weighted embedding sum (1 warp/group)
//    4 rows per iteration, batched online update
// -------------------------------------------------------------------------
__global__ void seg_softmax_kernel(const float* __restrict__ emb, int G) {
    int w = (blockIdx.x * blockDim.x + threadIdx.x) >> 5;
    int lane = threadIdx.x & 31;
    if (w >= G) return;

    int start = (w == 0) ? 0 : (g_last[w - 1] + 1);
    int end   = g_last[w];

    float4 pv = *(const float4*)(g_p + (size_t)w * D + (lane << 2));
    const float4* erow = (const float4*)emb;

    float m = -1e30f, denom = 0.f;
    float4 acc = {0.f, 0.f, 0.f, 0.f};

    for (int r = start; r <= end; r += 4) {
        int r1 = (r + 1 <= end) ? r + 1 : end;
        int r2 = (r + 2 <= end) ? r + 2 : end;
        int r3 = (r + 3 <= end) ? r + 3 : end;
        float4 c0 = erow[(size_t)r  * 32 + lane];
        float4 c1 = erow[(size_t)r1 * 32 + lane];
        float4 c2 = erow[(size_t)r2 * 32 + lane];
        float4 c3 = erow[(size_t)r3 * 32 + lane];

        float q0 = c0.x * pv.x + c0.y * pv.y + c0.z * pv.z + c0.w * pv.w;
        float q1 = c1.x * pv.x + c1.y * pv.y + c1.z * pv.z + c1.w * pv.w;
        float q2 = c2.x * pv.x + c2.y * pv.y + c2.z * pv.z + c2.w * pv.w;
        float q3 = c3.x * pv.x + c3.y * pv.y + c3.z * pv.z + c3.w * pv.w;
#pragma unroll
        for (int off = 16; off > 0; off >>= 1) {
            q0 += __shfl_xor_sync(0xffffffffu, q0, off);
            q1 += __shfl_xor_sync(0xffffffffu, q1, off);
            q2 += __shfl_xor_sync(0xffffffffu, q2, off);
            q3 += __shfl_xor_sync(0xffffffffu, q3, off);
        }
        // mask duplicated (clamped) rows out
        if (r + 1 > end) q1 = -1e30f;
        if (r + 2 > end) q2 = -1e30f;
        if (r + 3 > end) q3 = -1e30f;

        float mnew = fmaxf(fmaxf(fmaxf(m, q0), fmaxf(q1, q2)), q3);
        float scale = __expf(m - mnew);
        float w0 = __expf(q0 - mnew);
        float w1 = __expf(q1 - mnew);
        float w2 = __expf(q2 - mnew);
        float w3 = __expf(q3 - mnew);
        denom = denom * scale + ((w0 + w1) + (w2 + w3));
        acc.x = acc.x * scale + w0 * c0.x + w1 * c1.x + w2 * c2.x + w3 * c3.x;
        acc.y = acc.y * scale + w0 * c0.y + w1 * c1.y + w2 * c2.y + w3 * c3.y;
        acc.z = acc.z * scale + w0 * c0.z + w1 * c1.z + w2 * c2.z + w3 * c3.z;
        acc.w = acc.w * scale + w0 * c0.w + w1 * c1.w + w2 * c2.w + w3 * c3.w;
        m = mnew;
    }

    float inv = 1.0f / denom;
    float4 o = {acc.x * inv, acc.y * inv, acc.z * inv, acc.w * inv};
    *(float4*)(g_s + (size_t)w * D + (lane << 2)) = o;
}

// -------------------------------------------------------------------------
extern "C" void kernel_launch(void* const* d_in, const int* in_sizes, int n_in,
                              void* d_out, int out_size) {
    const float* emb = (const float*)d_in[0];
    const int*   seg = (const int*)d_in[1];
    const float* Wq  = (const float*)d_in[2];
    const float* bq  = (const float*)d_in[3];
    const float* Wk  = (const float*)d_in[4];
    const float* bk  = (const float*)d_in[5];
    float* out = (float*)d_out;

    int N = in_sizes[0] / D;
    int G = out_size / D;

    static bool attr_done = false;
    if (!attr_done) {
        cudaFuncSetAttribute(mma_gemm_kernel,
                             cudaFuncAttributeMaxDynamicSharedMemorySize, SMEM_TOT);
        attr_done = true;
    }

    void *pLast, *pBp, *pP, *pS, *pB1h, *pB1l, *pB2h, *pB2l;
    cudaGetSymbolAddress(&pLast, g_last);
    cudaGetSymbolAddress(&pBp, g_bp);
    cudaGetSymbolAddress(&pP, g_p);
    cudaGetSymbolAddress(&pS, g_s);
    cudaGetSymbolAddress(&pB1h, g_B1h);
    cudaGetSymbolAddress(&pB1l, g_B1l);
    cudaGetSymbolAddress(&pB2h, g_B2h);
    cudaGetSymbolAddress(&pB2l, g_B2l);

    bounds_kernel<<<(N + 255) / 256, 256>>>(seg, N);
    prep_kernel<<<65, 256>>>(Wq, bq, Wk);
    split_kernel<<<64, 256>>>(Wk);

    int nblk = (G + 127) / 128;

    // p[G,128] = emb[last] @ Aqk + b'
    mma_gemm_kernel<<<nblk, 256, SMEM_TOT>>>(
        emb, (const __nv_bfloat16*)pB1h, (const __nv_bfloat16*)pB1l,
        (const float*)pBp, (const int*)pLast, (float*)pP, G);

    // fused segment softmax -> s[G,128]
    seg_softmax_kernel<<<(G + 7) / 8, 256>>>(emb, G);

    // out = s @ Wk^T + bk
    mma_gemm_kernel<<<nblk, 256, SMEM_TOT>>>(
        (const float*)pS, (const __nv_bfloat16*)pB2h, (const __nv_bfloat16*)pB2l,
        bk, nullptr, out, G);
}

// round 13
// speedup vs baseline: 1.0563x; 1.0563x over previous
#include <cuda_runtime.h>
#include <cuda_bf16.h>
#include <cstddef>
#include <cstdint>

#define D 128
#define MAXG 100000

// scratch (device globals — no allocation allowed)
__device__ int   g_last[MAXG];
__device__ float g_A[D * D];
__device__ float g_bp[D];
__device__ float g_p[(size_t)MAXG * D];
__device__ float g_s[(size_t)MAXG * D];
// bf16 hi/lo splits of the two B matrices, stored as b_eff[n][k]
__device__ __nv_bfloat16 g_B1h[D * D], g_B1l[D * D];
__device__ __nv_bfloat16 g_B2h[D * D], g_B2l[D * D];

// ---------------------------------------------------------------- helpers
__device__ __forceinline__ float lo_of(float v) {
    return v - __bfloat162float(__float2bfloat16(v));
}
__device__ __forceinline__ uint32_t pack2(float a, float b) {
    __nv_bfloat162 h;
    h.x = __float2bfloat16(a);
    h.y = __float2bfloat16(b);
    return *(uint32_t*)&h;
}
__device__ __forceinline__ uint32_t smem_u32(const void* p) {
    uint32_t a;
    asm("{ .reg .u64 t; cvta.to.shared.u64 t, %1; cvt.u32.u64 %0, t; }"
        : "=r"(a) : "l"(p));
    return a;
}

#define MMA_BF16(cc, a0, a1, a2, a3, b0, b1)                                  \
    asm volatile(                                                             \
        "mma.sync.aligned.m16n8k16.row.col.f32.bf16.bf16.f32 "                \
        "{%0,%1,%2,%3}, {%4,%5,%6,%7}, {%8,%9}, {%0,%1,%2,%3};"               \
        : "+f"(cc[0]), "+f"(cc[1]), "+f"(cc[2]), "+f"(cc[3])                  \
        : "r"(a0), "r"(a1), "r"(a2), "r"(a3), "r"(b0), "r"(b1))

#define LDSM_X4(r, addr)                                                      \
    asm volatile("ldmatrix.sync.aligned.m8n8.x4.shared.b16 {%0,%1,%2,%3}, [%4];" \
                 : "=r"(r[0]), "=r"(r[1]), "=r"(r[2]), "=r"(r[3])             \
                 : "r"(addr))

// -------------------------------------------------------------------------
// 1) segment boundaries
// -------------------------------------------------------------------------
__global__ void bounds_kernel(const int* __restrict__ seg, int N) {
    int i = blockIdx.x * blockDim.x + threadIdx.x;
    if (i < N) {
        int sid = seg[i];
        if (i == N - 1 || seg[i + 1] != sid) g_last[sid] = i;
    }
}

// -------------------------------------------------------------------------
// 2) A = Wq^T @ Wk, b' = bq @ Wk
// -------------------------------------------------------------------------
__global__ void prep_kernel(const float* __restrict__ Wq, const float* __restrict__ bq,
                            const float* __restrict__ Wk) {
    int t = threadIdx.x;
    if (blockIdx.x < 64) {
        int idx = blockIdx.x * 256 + t;
        int i = idx >> 7, j = idx & 127;
        float sum = 0.f;
#pragma unroll 8
        for (int d = 0; d < D; d++) sum += Wq[d * D + i] * Wk[d * D + j];
        g_A[idx] = sum;
    } else if (t < D) {
        float sum = 0.f;
#pragma unroll 8
        for (int d = 0; d < D; d++) sum += bq[d] * Wk[d * D + t];
        g_bp[t] = sum;
    }
}

// -------------------------------------------------------------------------
// 2b) bf16 hi/lo split of both B matrices (b_eff[n][k] layout)
// -------------------------------------------------------------------------
__global__ void split_kernel(const float* __restrict__ Wk) {
    int idx = blockIdx.x * 256 + threadIdx.x;
    int n = idx >> 7, k = idx & 127;
    float v1 = g_A[k * D + n];
    g_B1h[idx] = __float2bfloat16(v1);
    g_B1l[idx] = __float2bfloat16(lo_of(v1));
    float v2 = Wk[idx];
    g_B2h[idx] = __float2bfloat16(v2);
    g_B2l[idx] = __float2bfloat16(lo_of(v2));
}

// -------------------------------------------------------------------------
// Tensor-core GEMM via mma.sync + ldmatrix:
//   C[M,128] = rows(Amat) @ b_eff^T + bias
//   3-term bf16 split (hi*hi + lo*hi + hi*lo), fp32 accumulate.
//   B staged ONCE in SMEM (full K).  A fragments loaded DIRECTLY from global
//   (coalesced LDG.64 per fragment slot), converted in registers — no A
//   staging, no A ldmatrix, a single __syncthreads in the whole kernel.
//   CTA tile 128x128, 256 thr, warp tile 32x64, 1-k-step A prefetch.
// -------------------------------------------------------------------------
#define BSROW  272                    // B row stride bytes (256 + 16)
#define OFF_BH 0
#define OFF_BL (128 * BSROW)          // 34816
#define SMEM_TOT (2 * 128 * BSROW)    // 69632 B -> 2 CTAs/SM (regs-bound)

__global__ void __launch_bounds__(256, 2)
mma_gemm_kernel(const float* __restrict__ Amat,
                const __nv_bfloat16* __restrict__ Bh,
                const __nv_bfloat16* __restrict__ Bl,
                const float* __restrict__ bias,
                const int* __restrict__ ridx,
                float* __restrict__ C, int M) {
    extern __shared__ char smem[];
    uint32_t sb = smem_u32(smem);
    int t = threadIdx.x, lane = t & 31, w = t >> 5;
    int mBase = blockIdx.x * 128;

    // compute mapping: warp (w&3) -> m rows [32), (w>>2) -> n cols [64)
    int warpM = (w & 3) * 32;
    int warpN = (w >> 2) * 64;
    int g = lane >> 2, p = lane & 3;

    // A row pointers: slots {mb0:g, mb0:g+8, mb1:g+16, mb1:g+24}
    const char* ar[4];
#pragma unroll
    for (int i = 0; i < 4; i++) {
        int m = mBase + warpM + i * 8 + g;
        if (m >= M) m = M - 1;
        int rr = ridx ? ridx[m] : m;
        ar[i] = (const char*)(Amat + (size_t)rr * D);
    }

    // prefetch A k-step 0 (before barrier; independent of SMEM)
    // af[mb][slot]: slot 0 = row g, k-lo; 1 = row g+8, k-lo; 2 = row g, k-hi; 3 = row g+8, k-hi
    float2 af[2][4];
#pragma unroll
    for (int mb = 0; mb < 2; mb++) {
        af[mb][0] = *(const float2*)(ar[mb * 2 + 0] + p * 8);
        af[mb][1] = *(const float2*)(ar[mb * 2 + 1] + p * 8);
        af[mb][2] = *(const float2*)(ar[mb * 2 + 0] + p * 8 + 32);
        af[mb][3] = *(const float2*)(ar[mb * 2 + 1] + p * 8 + 32);
    }

    // ---- stage B (full K, hi+lo), one time ----
    {
        int row = t >> 1, half = t & 1;
        const uint4* bhp = (const uint4*)(Bh + row * D + half * 64);
        const uint4* blp = (const uint4*)(Bl + row * D + half * 64);
        uint4* dh = (uint4*)(smem + OFF_BH + row * BSROW + half * 128);
        uint4* dl = (uint4*)(smem + OFF_BL + row * BSROW + half * 128);
#pragma unroll
        for (int j = 0; j < 8; j++) {
            dh[j] = bhp[j];
            dl[j] = blp[j];
        }
    }
    __syncthreads();

    int ldRow = (lane & 7) + 8 * ((lane >> 3) & 1);
    int ldK16 = (lane >> 4) * 16;
    uint32_t bOff = (uint32_t)((warpN + ldRow) * BSROW + ldK16);

    float acc[2][8][4];
#pragma unroll
    for (int mb = 0; mb < 2; mb++)
#pragma unroll
        for (int nb = 0; nb < 8; nb++)
#pragma unroll
            for (int i = 0; i < 4; i++) acc[mb][nb][i] = 0.f;

#pragma unroll
    for (int ks = 0; ks < 8; ks++) {
        // convert current A fragments to bf16 hi/lo
        uint32_t ah[2][4], al[2][4];
#pragma unroll
        for (int mb = 0; mb < 2; mb++)
#pragma unroll
            for (int s = 0; s < 4; s++) {
                float2 v = af[mb][s];
                ah[mb][s] = pack2(v.x, v.y);
                al[mb][s] = pack2(lo_of(v.x), lo_of(v.y));
            }
        // prefetch next k-step
        if (ks < 7) {
            int off = (ks + 1) * 64 + p * 8;
#pragma unroll
            for (int mb = 0; mb < 2; mb++) {
                af[mb][0] = *(const float2*)(ar[mb * 2 + 0] + off);
                af[mb][1] = *(const float2*)(ar[mb * 2 + 1] + off);
                af[mb][2] = *(const float2*)(ar[mb * 2 + 0] + off + 32);
                af[mb][3] = *(const float2*)(ar[mb * 2 + 1] + off + 32);
            }
        }
        // B fragments from SMEM + MMAs
        uint32_t kB = ks * 32;
#pragma unroll
        for (int nb2 = 0; nb2 < 4; nb2++) {
            uint32_t base = bOff + nb2 * (16 * BSROW) + kB;
            uint32_t bh[4], bl[4];
            LDSM_X4(bh, sb + OFF_BH + base);
            LDSM_X4(bl, sb + OFF_BL + base);
#pragma unroll
            for (int mb = 0; mb < 2; mb++) {
                MMA_BF16(acc[mb][nb2 * 2],     ah[mb][0], ah[mb][1], ah[mb][2], ah[mb][3], bh[0], bh[2]);
                MMA_BF16(acc[mb][nb2 * 2],     al[mb][0], al[mb][1], al[mb][2], al[mb][3], bh[0], bh[2]);
                MMA_BF16(acc[mb][nb2 * 2],     ah[mb][0], ah[mb][1], ah[mb][2], ah[mb][3], bl[0], bl[2]);
                MMA_BF16(acc[mb][nb2 * 2 + 1], ah[mb][0], ah[mb][1], ah[mb][2], ah[mb][3], bh[1], bh[3]);
                MMA_BF16(acc[mb][nb2 * 2 + 1], al[mb][0], al[mb][1], al[mb][2], al[mb][3], bh[1], bh[3]);
                MMA_BF16(acc[mb][nb2 * 2 + 1], ah[mb][0], ah[mb][1], ah[mb][2], ah[mb][3], bl[1], bl[3]);
            }
        }
    }

    // ---- epilogue ----
#pragma unroll
    for (int mb = 0; mb < 2; mb++) {
        int r0 = mBase + warpM + mb * 16 + g;
        int r1 = r0 + 8;
#pragma unroll
        for (int nb = 0; nb < 8; nb++) {
            int col = warpN + nb * 8 + p * 2;
            float2 bv = *(const float2*)(bias + col);
            if (r0 < M) {
                float2 o = {acc[mb][nb][0] + bv.x, acc[mb][nb][1] + bv.y};
                *(float2*)(C + (size_t)r0 * D + col) = o;
            }
            if (r1 < M) {
                float2 o = {acc[mb][nb][2] + bv.x, acc[mb][nb][3] + bv.y};
                *(float2*)(C + (size_t)r1 * D + col) = o;
            }
        }
    }
}

// -------------------------------------------------------------------------
// 4) fused per-segment online softmax + weighted embedding sum.
//    2 groups per warp (16 lanes each, 8 floats/lane), 2-row unroll.
// -------------------------------------------------------------------------
__global__ void seg_softmax_kernel(const float* __restrict__ emb, int G) {
    int w = (blockIdx.x * blockDim.x + threadIdx.x) >> 5;
    int lane = threadIdx.x & 31;
    if (2 * w >= G) return;
    int sub = lane >> 4, sl = lane & 15;
    int grp = 2 * w + sub;
    bool valid = grp < G;
    int gg = valid ? grp : G - 1;
    unsigned gmask = 0xFFFFu << (sub * 16);

    int start = (gg == 0) ? 0 : (g_last[gg - 1] + 1);
    int end   = g_last[gg];

    const float4* pvp = (const float4*)(g_p + (size_t)gg * D + sl * 8);
    float4 pv0 = pvp[0], pv1 = pvp[1];
    const float4* erow = (const float4*)emb;  // index = r*32 + sl*2 (+1)

    float m = -1e30f, denom = 0.f;
    float4 a0 = {0.f, 0.f, 0.f, 0.f}, a1 = {0.f, 0.f, 0.f, 0.f};

    for (int r = start; r <= end; r += 2) {
        int rb = (r + 1 <= end) ? r + 1 : end;
        float4 c00 = erow[(size_t)r  * 32 + sl * 2];
        float4 c01 = erow[(size_t)r  * 32 + sl * 2 + 1];
        float4 c10 = erow[(size_t)rb * 32 + sl * 2];
        float4 c11 = erow[(size_t)rb * 32 + sl * 2 + 1];

        float q0 = c00.x * pv0.x + c00.y * pv0.y + c00.z * pv0.z + c00.w * pv0.w
                 + c01.x * pv1.x + c01.y * pv1.y + c01.z * pv1.z + c01.w * pv1.w;
        float q1 = c10.x * pv0.x + c10.y * pv0.y + c10.z * pv0.z + c10.w * pv0.w
                 + c11.x * pv1.x + c11.y * pv1.y + c11.z * pv1.z + c11.w * pv1.w;
#pragma unroll
        for (int off = 8; off > 0; off >>= 1) {
            q0 += __shfl_xor_sync(gmask, q0, off);
            q1 += __shfl_xor_sync(gmask, q1, off);
        }
        if (r + 1 > end) q1 = -1e30f;

        float mnew = fmaxf(m, fmaxf(q0, q1));
        float sc = __expf(m - mnew);
        float w0 = __expf(q0 - mnew);
        float w1 = __expf(q1 - mnew);
        denom = denom * sc + (w0 + w1);
        a0.x = a0.x * sc + w0 * c00.x + w1 * c10.x;
        a0.y = a0.y * sc + w0 * c00.y + w1 * c10.y;
        a0.z = a0.z * sc + w0 * c00.z + w1 * c10.z;
        a0.w = a0.w * sc + w0 * c00.w + w1 * c10.w;
        a1.x = a1.x * sc + w0 * c01.x + w1 * c11.x;
        a1.y = a1.y * sc + w0 * c01.y + w1 * c11.y;
        a1.z = a1.z * sc + w0 * c01.z + w1 * c11.z;
        a1.w = a1.w * sc + w0 * c01.w + w1 * c11.w;
        m = mnew;
    }

    if (valid) {
        float inv = 1.0f / denom;
        float4 o0 = {a0.x * inv, a0.y * inv, a0.z * inv, a0.w * inv};
        float4 o1 = {a1.x * inv, a1.y * inv, a1.z * inv, a1.w * inv};
        float4* sp = (float4*)(g_s + (size_t)gg * D + sl * 8);
        sp[0] = o0;
        sp[1] = o1;
    }
}

// -------------------------------------------------------------------------
extern "C" void kernel_launch(void* const* d_in, const int* in_sizes, int n_in,
                              void* d_out, int out_size) {
    const float* emb = (const float*)d_in[0];
    const int*   seg = (const int*)d_in[1];
    const float* Wq  = (const float*)d_in[2];
    const float* bq  = (const float*)d_in[3];
    const float* Wk  = (const float*)d_in[4];
    const float* bk  = (const float*)d_in[5];
    float* out = (float*)d_out;

    int N = in_sizes[0] / D;
    int G = out_size / D;

    static bool attr_done = false;
    if (!attr_done) {
        cudaFuncSetAttribute(mma_gemm_kernel,
                             cudaFuncAttributeMaxDynamicSharedMemorySize, SMEM_TOT);
        attr_done = true;
    }

    void *pLast, *pBp, *pP, *pS, *pB1h, *pB1l, *pB2h, *pB2l;
    cudaGetSymbolAddress(&pLast, g_last);
    cudaGetSymbolAddress(&pBp, g_bp);
    cudaGetSymbolAddress(&pP, g_p);
    cudaGetSymbolAddress(&pS, g_s);
    cudaGetSymbolAddress(&pB1h, g_B1h);
    cudaGetSymbolAddress(&pB1l, g_B1l);
    cudaGetSymbolAddress(&pB2h, g_B2h);
    cudaGetSymbolAddress(&pB2l, g_B2l);

    bounds_kernel<<<(N + 255) / 256, 256>>>(seg, N);
    prep_kernel<<<65, 256>>>(Wq, bq, Wk);
    split_kernel<<<64, 256>>>(Wk);

    int nblk = (G + 127) / 128;

    // p[G,128] = emb[last] @ Aqk + b'
    mma_gemm_kernel<<<nblk, 256, SMEM_TOT>>>(
        emb, (const __nv_bfloat16*)pB1h, (const __nv_bfloat16*)pB1l,
        (const float*)pBp, (const int*)pLast, (float*)pP, G);

    // fused segment softmax -> s[G,128]  (2 groups per warp)
    seg_softmax_kernel<<<(G + 15) / 16, 256>>>(emb, G);

    // out = s @ Wk^T + bk
    mma_gemm_kernel<<<nblk, 256, SMEM_TOT>>>(
        (const float*)pS, (const __nv_bfloat16*)pB2h, (const __nv_bfloat16*)pB2l,
        bk, nullptr, out, G);
}

// round 14
// speedup vs baseline: 1.0705x; 1.0134x over previous
#include <cuda_runtime.h>
#include <cuda_bf16.h>
#include <cstddef>
#include <cstdint>

#define D 128
#define MAXG 100000

// scratch (device globals — no allocation allowed)
__device__ int   g_last[MAXG];
__device__ float g_A[D * D];
__device__ float g_bp[D];
__device__ float g_p[(size_t)MAXG * D];
__device__ float g_s[(size_t)MAXG * D];
// bf16 hi/lo splits of the two B matrices, stored as b_eff[n][k]
__device__ __nv_bfloat16 g_B1h[D * D], g_B1l[D * D];
__device__ __nv_bfloat16 g_B2h[D * D], g_B2l[D * D];

// ---------------------------------------------------------------- helpers
__device__ __forceinline__ float lo_of(float v) {
    return v - __bfloat162float(__float2bfloat16(v));
}
__device__ __forceinline__ uint32_t pack2(float a, float b) {
    __nv_bfloat162 h;
    h.x = __float2bfloat16(a);
    h.y = __float2bfloat16(b);
    return *(uint32_t*)&h;
}
__device__ __forceinline__ uint32_t smem_u32(const void* p) {
    uint32_t a;
    asm("{ .reg .u64 t; cvta.to.shared.u64 t, %1; cvt.u32.u64 %0, t; }"
        : "=r"(a) : "l"(p));
    return a;
}

#define MMA_BF16(cc, a0, a1, a2, a3, b0, b1)                                  \
    asm volatile(                                                             \
        "mma.sync.aligned.m16n8k16.row.col.f32.bf16.bf16.f32 "                \
        "{%0,%1,%2,%3}, {%4,%5,%6,%7}, {%8,%9}, {%0,%1,%2,%3};"               \
        : "+f"(cc[0]), "+f"(cc[1]), "+f"(cc[2]), "+f"(cc[3])                  \
        : "r"(a0), "r"(a1), "r"(a2), "r"(a3), "r"(b0), "r"(b1))

#define LDSM_X4(r, addr)                                                      \
    asm volatile("ldmatrix.sync.aligned.m8n8.x4.shared.b16 {%0,%1,%2,%3}, [%4];" \
                 : "=r"(r[0]), "=r"(r[1]), "=r"(r[2]), "=r"(r[3])             \
                 : "r"(addr))

// -------------------------------------------------------------------------
// 1) segment boundaries
// -------------------------------------------------------------------------
__global__ void bounds_kernel(const int* __restrict__ seg, int N) {
    int i = blockIdx.x * blockDim.x + threadIdx.x;
    if (i < N) {
        int sid = seg[i];
        if (i == N - 1 || seg[i + 1] != sid) g_last[sid] = i;
    }
}

// -------------------------------------------------------------------------
// 2) A = Wq^T @ Wk, b' = bq @ Wk
// -------------------------------------------------------------------------
__global__ void prep_kernel(const float* __restrict__ Wq, const float* __restrict__ bq,
                            const float* __restrict__ Wk) {
    int t = threadIdx.x;
    if (blockIdx.x < 64) {
        int idx = blockIdx.x * 256 + t;
        int i = idx >> 7, j = idx & 127;
        float sum = 0.f;
#pragma unroll 8
        for (int d = 0; d < D; d++) sum += Wq[d * D + i] * Wk[d * D + j];
        g_A[idx] = sum;
    } else if (t < D) {
        float sum = 0.f;
#pragma unroll 8
        for (int d = 0; d < D; d++) sum += bq[d] * Wk[d * D + t];
        g_bp[t] = sum;
    }
}

// -------------------------------------------------------------------------
// 2b) bf16 hi/lo split of both B matrices (b_eff[n][k] layout)
// -------------------------------------------------------------------------
__global__ void split_kernel(const float* __restrict__ Wk) {
    int idx = blockIdx.x * 256 + threadIdx.x;
    int n = idx >> 7, k = idx & 127;
    float v1 = g_A[k * D + n];
    g_B1h[idx] = __float2bfloat16(v1);
    g_B1l[idx] = __float2bfloat16(lo_of(v1));
    float v2 = Wk[idx];
    g_B2h[idx] = __float2bfloat16(v2);
    g_B2l[idx] = __float2bfloat16(lo_of(v2));
}

// -------------------------------------------------------------------------
// Tensor-core GEMM via mma.sync + ldmatrix:
//   C[M,128] = rows(Amat) @ b_eff^T + bias
//   3-term bf16 split (hi*hi + lo*hi + hi*lo), fp32 accumulate.
//   B staged ONCE in SMEM (full K); A fragments loaded directly from global.
//   B fragments software-pipelined (register ping-pong, 1 group ahead).
//   MMAs ordered by split term so same-acc MMAs are 4 issues apart.
//   CTA tile 128x128, 256 thr, warp tile 32x64, 1-k-step A prefetch.
// -------------------------------------------------------------------------
#define BSROW  272                    // B row stride bytes (256 + 16)
#define OFF_BH 0
#define OFF_BL (128 * BSROW)          // 34816
#define SMEM_TOT (2 * 128 * BSROW)    // 69632 B -> 2 CTAs/SM (regs-bound)

__global__ void __launch_bounds__(256, 2)
mma_gemm_kernel(const float* __restrict__ Amat,
                const __nv_bfloat16* __restrict__ Bh,
                const __nv_bfloat16* __restrict__ Bl,
                const float* __restrict__ bias,
                const int* __restrict__ ridx,
                float* __restrict__ C, int M) {
    extern __shared__ char smem[];
    uint32_t sb = smem_u32(smem);
    int t = threadIdx.x, lane = t & 31, w = t >> 5;
    int mBase = blockIdx.x * 128;

    // compute mapping: warp (w&3) -> m rows [32), (w>>2) -> n cols [64)
    int warpM = (w & 3) * 32;
    int warpN = (w >> 2) * 64;
    int g = lane >> 2, p = lane & 3;

    // A row pointers: slots {mb0:g, mb0:g+8, mb1:g+16, mb1:g+24}
    const char* ar[4];
#pragma unroll
    for (int i = 0; i < 4; i++) {
        int m = mBase + warpM + i * 8 + g;
        if (m >= M) m = M - 1;
        int rr = ridx ? ridx[m] : m;
        ar[i] = (const char*)(Amat + (size_t)rr * D);
    }

    // prefetch A k-step 0 (before barrier; independent of SMEM)
    float2 af[2][4];
#pragma unroll
    for (int mb = 0; mb < 2; mb++) {
        af[mb][0] = *(const float2*)(ar[mb * 2 + 0] + p * 8);
        af[mb][1] = *(const float2*)(ar[mb * 2 + 1] + p * 8);
        af[mb][2] = *(const float2*)(ar[mb * 2 + 0] + p * 8 + 32);
        af[mb][3] = *(const float2*)(ar[mb * 2 + 1] + p * 8 + 32);
    }

    // ---- stage B (full K, hi+lo), one time ----
    {
        int row = t >> 1, half = t & 1;
        const uint4* bhp = (const uint4*)(Bh + row * D + half * 64);
        const uint4* blp = (const uint4*)(Bl + row * D + half * 64);
        uint4* dh = (uint4*)(smem + OFF_BH + row * BSROW + half * 128);
        uint4* dl = (uint4*)(smem + OFF_BL + row * BSROW + half * 128);
#pragma unroll
        for (int j = 0; j < 8; j++) {
            dh[j] = bhp[j];
            dl[j] = blp[j];
        }
    }
    __syncthreads();

    int ldRow = (lane & 7) + 8 * ((lane >> 3) & 1);
    int ldK16 = (lane >> 4) * 16;
    uint32_t bOff = sb + (uint32_t)((warpN + ldRow) * BSROW + ldK16);

    float acc[2][8][4];
#pragma unroll
    for (int mb = 0; mb < 2; mb++)
#pragma unroll
        for (int nb = 0; nb < 8; nb++)
#pragma unroll
            for (int i = 0; i < 4; i++) acc[mb][nb][i] = 0.f;

    // B fragment ping-pong buffers; preload (ks=0, nb2=0) into buf 0
    uint32_t bh[2][4], bl[2][4];
    LDSM_X4(bh[0], bOff + OFF_BH);
    LDSM_X4(bl[0], bOff + OFF_BL);

#pragma unroll
    for (int ks = 0; ks < 8; ks++) {
        // convert current A fragments to bf16 hi/lo
        uint32_t ah[2][4], al[2][4];
#pragma unroll
        for (int mb = 0; mb < 2; mb++)
#pragma unroll
            for (int s = 0; s < 4; s++) {
                float2 v = af[mb][s];
                ah[mb][s] = pack2(v.x, v.y);
                al[mb][s] = pack2(lo_of(v.x), lo_of(v.y));
            }
        // prefetch next k-step's A
        if (ks < 7) {
            int off = (ks + 1) * 64 + p * 8;
#pragma unroll
            for (int mb = 0; mb < 2; mb++) {
                af[mb][0] = *(const float2*)(ar[mb * 2 + 0] + off);
                af[mb][1] = *(const float2*)(ar[mb * 2 + 1] + off);
                af[mb][2] = *(const float2*)(ar[mb * 2 + 0] + off + 32);
                af[mb][3] = *(const float2*)(ar[mb * 2 + 1] + off + 32);
            }
        }
#pragma unroll
        for (int nb2 = 0; nb2 < 4; nb2++) {
            int cur = (ks * 4 + nb2) & 1;
            int nxt = cur ^ 1;
            // prefetch next B fragment group (crosses kstep boundary)
            if (!(ks == 7 && nb2 == 3)) {
                int nks = (nb2 == 3) ? ks + 1 : ks;
                int nnb = (nb2 == 3) ? 0 : nb2 + 1;
                uint32_t nb_off = bOff + (uint32_t)(nnb * (16 * BSROW) + nks * 32);
                LDSM_X4(bh[nxt], nb_off + OFF_BH);
                LDSM_X4(bl[nxt], nb_off + OFF_BL);
            }
            int n0 = nb2 * 2, n1 = nb2 * 2 + 1;
            // term hh (4 independent accs)
            MMA_BF16(acc[0][n0], ah[0][0], ah[0][1], ah[0][2], ah[0][3], bh[cur][0], bh[cur][2]);
            MMA_BF16(acc[0][n1], ah[0][0], ah[0][1], ah[0][2], ah[0][3], bh[cur][1], bh[cur][3]);
            MMA_BF16(acc[1][n0], ah[1][0], ah[1][1], ah[1][2], ah[1][3], bh[cur][0], bh[cur][2]);
            MMA_BF16(acc[1][n1], ah[1][0], ah[1][1], ah[1][2], ah[1][3], bh[cur][1], bh[cur][3]);
            // term lh
            MMA_BF16(acc[0][n0], al[0][0], al[0][1], al[0][2], al[0][3], bh[cur][0], bh[cur][2]);
            MMA_BF16(acc[0][n1], al[0][0], al[0][1], al[0][2], al[0][3], bh[cur][1], bh[cur][3]);
            MMA_BF16(acc[1][n0], al[1][0], al[1][1], al[1][2], al[1][3], bh[cur][0], bh[cur][2]);
            MMA_BF16(acc[1][n1], al[1][0], al[1][1], al[1][2], al[1][3], bh[cur][1], bh[cur][3]);
            // term hl
            MMA_BF16(acc[0][n0], ah[0][0], ah[0][1], ah[0][2], ah[0][3], bl[cur][0], bl[cur][2]);
            MMA_BF16(acc[0][n1], ah[0][0], ah[0][1], ah[0][2], ah[0][3], bl[cur][1], bl[cur][3]);
            MMA_BF16(acc[1][n0], ah[1][0], ah[1][1], ah[1][2], ah[1][3], bl[cur][0], bl[cur][2]);
            MMA_BF16(acc[1][n1], ah[1][0], ah[1][1], ah[1][2], ah[1][3], bl[cur][1], bl[cur][3]);
        }
    }

    // ---- epilogue ----
#pragma unroll
    for (int mb = 0; mb < 2; mb++) {
        int r0 = mBase + warpM + mb * 16 + g;
        int r1 = r0 + 8;
#pragma unroll
        for (int nb = 0; nb < 8; nb++) {
            int col = warpN + nb * 8 + p * 2;
            float2 bv = *(const float2*)(bias + col);
            if (r0 < M) {
                float2 o = {acc[mb][nb][0] + bv.x, acc[mb][nb][1] + bv.y};
                *(float2*)(C + (size_t)r0 * D + col) = o;
            }
            if (r1 < M) {
                float2 o = {acc[mb][nb][2] + bv.x, acc[mb][nb][3] + bv.y};
                *(float2*)(C + (size_t)r1 * D + col) = o;
            }
        }
    }
}

// -------------------------------------------------------------------------
// 4) fused per-segment online softmax + weighted embedding sum.
//    2 groups per warp (16 lanes each, 8 floats/lane), 4-row unroll.
// -------------------------------------------------------------------------
__global__ void seg_softmax_kernel(const float* __restrict__ emb, int G) {
    int w = (blockIdx.x * blockDim.x + threadIdx.x) >> 5;
    int lane = threadIdx.x & 31;
    if (2 * w >= G) return;
    int sub = lane >> 4, sl = lane & 15;
    int grp = 2 * w + sub;
    bool valid = grp < G;
    int gg = valid ? grp : G - 1;
    unsigned gmask = 0xFFFFu << (sub * 16);

    int start = (gg == 0) ? 0 : (g_last[gg - 1] + 1);
    int end   = g_last[gg];

    const float4* pvp = (const float4*)(g_p + (size_t)gg * D + sl * 8);
    float4 pv0 = pvp[0], pv1 = pvp[1];
    const float4* erow = (const float4*)emb;  // index = r*32 + sl*2 (+1)

    float m = -1e30f, denom = 0.f;
    float4 a0 = {0.f, 0.f, 0.f, 0.f}, a1 = {0.f, 0.f, 0.f, 0.f};

    for (int r = start; r <= end; r += 4) {
        int rr1 = (r + 1 <= end) ? r + 1 : end;
        int rr2 = (r + 2 <= end) ? r + 2 : end;
        int rr3 = (r + 3 <= end) ? r + 3 : end;
        float4 c00 = erow[(size_t)r   * 32 + sl * 2];
        float4 c01 = erow[(size_t)r   * 32 + sl * 2 + 1];
        float4 c10 = erow[(size_t)rr1 * 32 + sl * 2];
        float4 c11 = erow[(size_t)rr1 * 32 + sl * 2 + 1];
        float4 c20 = erow[(size_t)rr2 * 32 + sl * 2];
        float4 c21 = erow[(size_t)rr2 * 32 + sl * 2 + 1];
        float4 c30 = erow[(size_t)rr3 * 32 + sl * 2];
        float4 c31 = erow[(size_t)rr3 * 32 + sl * 2 + 1];

        float q0 = c00.x * pv0.x + c00.y * pv0.y + c00.z * pv0.z + c00.w * pv0.w
                 + c01.x * pv1.x + c01.y * pv1.y + c01.z * pv1.z + c01.w * pv1.w;
        float q1 = c10.x * pv0.x + c10.y * pv0.y + c10.z * pv0.z + c10.w * pv0.w
                 + c11.x * pv1.x + c11.y * pv1.y + c11.z * pv1.z + c11.w * pv1.w;
        float q2 = c20.x * pv0.x + c20.y * pv0.y + c20.z * pv0.z + c20.w * pv0.w
                 + c21.x * pv1.x + c21.y * pv1.y + c21.z * pv1.z + c21.w * pv1.w;
        float q3 = c30.x * pv0.x + c30.y * pv0.y + c30.z * pv0.z + c30.w * pv0.w
                 + c31.x * pv1.x + c31.y * pv1.y + c31.z * pv1.z + c31.w * pv1.w;
#pragma unroll
        for (int off = 8; off > 0; off >>= 1) {
            q0 += __shfl_xor_sync(gmask, q0, off);
            q1 += __shfl_xor_sync(gmask, q1, off);
            q2 += __shfl_xor_sync(gmask, q2, off);
            q3 += __shfl_xor_sync(gmask, q3, off);
        }
        if (r + 1 > end) q1 = -1e30f;
        if (r + 2 > end) q2 = -1e30f;
        if (r + 3 > end) q3 = -1e30f;

        float mnew = fmaxf(fmaxf(fmaxf(m, q0), fmaxf(q1, q2)), q3);
        float sc = __expf(m - mnew);
        float w0 = __expf(q0 - mnew);
        float w1 = __expf(q1 - mnew);
        float w2 = __expf(q2 - mnew);
        float w3 = __expf(q3 - mnew);
        denom = denom * sc + ((w0 + w1) + (w2 + w3));
        a0.x = a0.x * sc + w0 * c00.x + w1 * c10.x + w2 * c20.x + w3 * c30.x;
        a0.y = a0.y * sc + w0 * c00.y + w1 * c10.y + w2 * c20.y + w3 * c30.y;
        a0.z = a0.z * sc + w0 * c00.z + w1 * c10.z + w2 * c20.z + w3 * c30.z;
        a0.w = a0.w * sc + w0 * c00.w + w1 * c10.w + w2 * c20.w + w3 * c30.w;
        a1.x = a1.x * sc + w0 * c01.x + w1 * c11.x + w2 * c21.x + w3 * c31.x;
        a1.y = a1.y * sc + w0 * c01.y + w1 * c11.y + w2 * c21.y + w3 * c31.y;
        a1.z = a1.z * sc + w0 * c01.z + w1 * c11.z + w2 * c21.z + w3 * c31.z;
        a1.w = a1.w * sc + w0 * c01.w + w1 * c11.w + w2 * c21.w + w3 * c31.w;
        m = mnew;
    }

    if (valid) {
        float inv = 1.0f / denom;
        float4 o0 = {a0.x * inv, a0.y * inv, a0.z * inv, a0.w * inv};
        float4 o1 = {a1.x * inv, a1.y * inv, a1.z * inv, a1.w * inv};
        float4* sp = (float4*)(g_s + (size_t)gg * D + sl * 8);
        sp[0] = o0;
        sp[1] = o1;
    }
}

// -------------------------------------------------------------------------
extern "C" void kernel_launch(void* const* d_in, const int* in_sizes, int n_in,
                              void* d_out, int out_size) {
    const float* emb = (const float*)d_in[0];
    const int*   seg = (const int*)d_in[1];
    const float* Wq  = (const float*)d_in[2];
    const float* bq  = (const float*)d_in[3];
    const float* Wk  = (const float*)d_in[4];
    const float* bk  = (const float*)d_in[5];
    float* out = (float*)d_out;

    int N = in_sizes[0] / D;
    int G = out_size / D;

    static bool attr_done = false;
    if (!attr_done) {
        cudaFuncSetAttribute(mma_gemm_kernel,
                             cudaFuncAttributeMaxDynamicSharedMemorySize, SMEM_TOT);
        attr_done = true;
    }

    void *pLast, *pBp, *pP, *pS, *pB1h, *pB1l, *pB2h, *pB2l;
    cudaGetSymbolAddress(&pLast, g_last);
    cudaGetSymbolAddress(&pBp, g_bp);
    cudaGetSymbolAddress(&pP, g_p);
    cudaGetSymbolAddress(&pS, g_s);
    cudaGetSymbolAddress(&pB1h, g_B1h);
    cudaGetSymbolAddress(&pB1l, g_B1l);
    cudaGetSymbolAddress(&pB2h, g_B2h);
    cudaGetSymbolAddress(&pB2l, g_B2l);

    bounds_kernel<<<(N + 255) / 256, 256>>>(seg, N);
    prep_kernel<<<65, 256>>>(Wq, bq, Wk);
    split_kernel<<<64, 256>>>(Wk);

    int nblk = (G + 127) / 128;

    // p[G,128] = emb[last] @ Aqk + b'
    mma_gemm_kernel<<<nblk, 256, SMEM_TOT>>>(
        emb, (const __nv_bfloat16*)pB1h, (const __nv_bfloat16*)pB1l,
        (const float*)pBp, (const int*)pLast, (float*)pP, G);

    // fused segment softmax -> s[G,128]  (2 groups per warp)
    seg_softmax_kernel<<<(G + 15) / 16, 256>>>(emb, G);

    // out = s @ Wk^T + bk
    mma_gemm_kernel<<<nblk, 256, SMEM_TOT>>>(
        (const float*)pS, (const __nv_bfloat16*)pB2h, (const __nv_bfloat16*)pB2l,
        bk, nullptr, out, G);
}